// round 6
// baseline (speedup 1.0000x reference)
#include <cuda_runtime.h>
#include <cuda_bf16.h>

#define NMAX   50000
#define EMAX   800000
#define INDIM  128
#define OUTDIM 64

// Scratch (device globals: allocation-free rule)
__device__ float  g_z[NMAX * OUTDIM];   // node features after W
__device__ float  g_s[NMAX];            // src-half attention proj
__device__ float  g_t[NMAX];            // dst-half attention proj
__device__ int    g_meta[NMAX + 1];     // [0,N): cnt  [N]: allocator total
__device__ int    g_off[NMAX];          // per-dst bucket base
__device__ int    g_rank[EMAX];         // per-edge rank within its dst bucket
__device__ float2 g_edge[EMAX];         // packed (src bits, ex) per edge

#define G_CNT   (g_meta)
#define G_TOTAL (g_meta + NMAX)

// ---------------------------------------------------------------------------
// f32x2 helpers (FFMA2 only reachable via PTX fma.rn.f32x2)
__device__ __forceinline__ unsigned long long splat2(float a) {
    unsigned long long r;
    asm("mov.b64 %0, {%1, %1};" : "=l"(r) : "f"(a));
    return r;
}
__device__ __forceinline__ void fma2(unsigned long long& d,
                                     unsigned long long a, unsigned long long b) {
    asm("fma.rn.f32x2 %0, %1, %2, %0;" : "+l"(d) : "l"(a), "l"(b));
}

// ---------------------------------------------------------------------------
// K1 (fused): blocks [0, NG) compute z = h @ W (+ s/t projections);
//             blocks [NG, NG+HB) do the in-degree histogram + per-edge rank.
__global__ __launch_bounds__(256) void k_fused(const float* __restrict__ h,
                                               const float* __restrict__ W,
                                               const float* __restrict__ Wa,
                                               const int4* __restrict__ dst4,
                                               int N, int E4, int NG) {
    __shared__ float2 sw2[INDIM * 33];

    if (blockIdx.x >= NG) {
        int t = (blockIdx.x - NG) * 256 + threadIdx.x;
        if (t < E4) {
            int4 d = __ldg(dst4 + t);
            int4 r;
            r.x = atomicAdd(&G_CNT[d.x], 1);
            r.y = atomicAdd(&G_CNT[d.y], 1);
            r.z = atomicAdd(&G_CNT[d.z], 1);
            r.w = atomicAdd(&G_CNT[d.w], 1);
            ((int4*)g_rank)[t] = r;
        }
        return;
    }

    // ---- GEMM half ----
    const int tid  = threadIdx.x;
    const int row0 = blockIdx.x * 64;

    const float2* W2 = (const float2*)W;
    for (int idx = tid; idx < INDIM * 32; idx += 256) {
        int k = idx >> 5, p = idx & 31;
        sw2[k * 33 + p] = W2[k * 32 + p];
    }
    __syncthreads();

    const int tx = tid & 15;
    const int ty = tid >> 4;

    int  rows[4];
    bool rv[4];
#pragma unroll
    for (int i = 0; i < 4; i++) { rows[i] = row0 + ty + 16 * i; rv[i] = rows[i] < N; }

    unsigned long long acc2[4][2];
#pragma unroll
    for (int i = 0; i < 4; i++) { acc2[i][0] = 0ull; acc2[i][1] = 0ull; }

    const float4 f4z = make_float4(0.f, 0.f, 0.f, 0.f);

#pragma unroll 4
    for (int k = 0; k < INDIM; k += 4) {
        float4 hv[4];
#pragma unroll
        for (int i = 0; i < 4; i++)
            hv[i] = rv[i] ? __ldg((const float4*)(h + (size_t)rows[i] * INDIM + k)) : f4z;
#pragma unroll
        for (int ks = 0; ks < 4; ks++) {
            unsigned long long w0 = *(const unsigned long long*)&sw2[(k + ks) * 33 + tx];
            unsigned long long w1 = *(const unsigned long long*)&sw2[(k + ks) * 33 + tx + 16];
#pragma unroll
            for (int i = 0; i < 4; i++) {
                const float* hp = &hv[i].x;
                unsigned long long aa = splat2(hp[ks]);
                fma2(acc2[i][0], aa, w0);
                fma2(acc2[i][1], aa, w1);
            }
        }
    }

    float wa_s[2][2], wa_t[2][2];
#pragma unroll
    for (int j = 0; j < 2; j++) {
        int c = (tx + 16 * j) * 2;
        wa_s[j][0] = __ldg(Wa + c);          wa_s[j][1] = __ldg(Wa + c + 1);
        wa_t[j][0] = __ldg(Wa + OUTDIM + c); wa_t[j][1] = __ldg(Wa + OUTDIM + c + 1);
    }

#pragma unroll
    for (int i = 0; i < 4; i++) {
        float2 a0 = *(float2*)&acc2[i][0];
        float2 a1 = *(float2*)&acc2[i][1];
        if (rv[i]) {
            float* zr = g_z + (size_t)rows[i] * OUTDIM;
            *(float2*)(zr + tx * 2)        = a0;
            *(float2*)(zr + (tx + 16) * 2) = a1;
        }
        float sp = a0.x * wa_s[0][0] + a0.y * wa_s[0][1]
                 + a1.x * wa_s[1][0] + a1.y * wa_s[1][1];
        float tp = a0.x * wa_t[0][0] + a0.y * wa_t[0][1]
                 + a1.x * wa_t[1][0] + a1.y * wa_t[1][1];
#pragma unroll
        for (int off = 8; off > 0; off >>= 1) {
            sp += __shfl_xor_sync(0xffffffffu, sp, off, 16);
            tp += __shfl_xor_sync(0xffffffffu, tp, off, 16);
        }
        if (tx == 0 && rv[i]) { g_s[rows[i]] = sp; g_t[rows[i]] = tp; }
    }
}

// ---------------------------------------------------------------------------
// K2: offsets: per-block inclusive scan + one allocator atomic per block.
__global__ __launch_bounds__(1024) void k_alloc(int N) {
    __shared__ int sd[1024];
    __shared__ int sbase;
    int t = threadIdx.x;
    int i = blockIdx.x * 1024 + t;
    int v = (i < N) ? G_CNT[i] : 0;
    sd[t] = v;
    __syncthreads();
#pragma unroll
    for (int d = 1; d < 1024; d <<= 1) {
        int x = (t >= d) ? sd[t - d] : 0;
        __syncthreads();
        sd[t] += x;
        __syncthreads();
    }
    if (t == 1023) sbase = atomicAdd(G_TOTAL, sd[1023]);
    __syncthreads();
    if (i < N) g_off[i] = sbase + sd[t] - v;
}

// ---------------------------------------------------------------------------
// K3: bucket fill, atomic-free: position = off[dst] + rank.
__global__ __launch_bounds__(256) void k_fill(const int* __restrict__ src,
                                              const int* __restrict__ dst,
                                              int E) {
    int i = blockIdx.x * blockDim.x + threadIdx.x;
    if (i >= E) return;
    int s = src[i];
    int d = dst[i];
    int r = g_rank[i];
    float ex = __expf(fmaxf(__ldg(g_s + s) + __ldg(g_t + d), 0.0f));
    int p = __ldg(g_off + d) + r;
    g_edge[p] = make_float2(__int_as_float(s), ex);
}

// ---------------------------------------------------------------------------
// K4: one warp per dst node. Half-warp split: half h handles edges of parity
//     h; each lane gathers one float4 of the z row (16 lanes = full 256B row).
//     Edge (src, ex) pairs come via uniform __ldg (L1 broadcast) — no smem,
//     no __syncwarp. den accumulates redundantly per lane; one xor-16 shuffle
//     merges halves at the end.
__global__ __launch_bounds__(256) void k_node(float* __restrict__ out, int N) {
    int warp = (blockIdx.x * blockDim.x + threadIdx.x) >> 5;
    int lane = threadIdx.x & 31;
    if (warp >= N) return;

    int beg  = g_off[warp];
    int deg  = G_CNT[warp];
    int q    = lane & 15;
    int half = lane >> 4;

    const float4* z4 = (const float4*)g_z;   // 16 float4 per z row
    float4 acc = make_float4(0.f, 0.f, 0.f, 0.f);
    float  den = 0.0f;

#pragma unroll 2
    for (int jb = 0; jb < deg; jb += 2) {
        int j = jb + half;
        if (j < deg) {
            float2 pr = __ldg(g_edge + beg + j);     // uniform per half-warp
            float  a  = pr.y;
            int    s2 = __float_as_int(pr.x);
            den += a;
            float4 v = __ldg(z4 + (size_t)s2 * 16 + q);
            acc.x += a * v.x;
            acc.y += a * v.y;
            acc.z += a * v.z;
            acc.w += a * v.w;
        }
    }

    // merge even/odd halves
    den   += __shfl_xor_sync(0xffffffffu, den,   16);
    acc.x += __shfl_xor_sync(0xffffffffu, acc.x, 16);
    acc.y += __shfl_xor_sync(0xffffffffu, acc.y, 16);
    acc.z += __shfl_xor_sync(0xffffffffu, acc.z, 16);
    acc.w += __shfl_xor_sync(0xffffffffu, acc.w, 16);

    if (half == 0) {
        float rden = (deg > 0) ? (1.0f / den) : 0.0f;
        float4 o;
        o.x = fmaxf(acc.x * rden, 0.0f);
        o.y = fmaxf(acc.y * rden, 0.0f);
        o.z = fmaxf(acc.z * rden, 0.0f);
        o.w = fmaxf(acc.w * rden, 0.0f);
        *(float4*)(out + (size_t)warp * OUTDIM + q * 4) = o;
    }
}

// ---------------------------------------------------------------------------
extern "C" void kernel_launch(void* const* d_in, const int* in_sizes, int n_in,
                              void* d_out, int out_size) {
    const float* h   = (const float*)d_in[0];
    const float* W   = (const float*)d_in[1];
    const float* Wa  = (const float*)d_in[2];
    const int*   src = (const int*)d_in[3];
    const int*   dst = (const int*)d_in[4];
    float* out = (float*)d_out;

    int N  = in_sizes[0] / INDIM;
    int E  = in_sizes[3];
    int E4 = E >> 2;
    int NB = (N + 1023) >> 10;
    int NG = (N + 63) / 64;
    int HB = (E4 + 255) / 256;

    void* meta_ptr = nullptr;
    cudaGetSymbolAddress(&meta_ptr, g_meta);
    cudaMemsetAsync(meta_ptr, 0, (NMAX + 1) * sizeof(int), 0);

    k_fused<<<NG + HB, 256>>>(h, W, Wa, (const int4*)dst, N, E4, NG);
    k_alloc<<<NB, 1024>>>(N);
    k_fill <<<(E + 255) / 256, 256>>>(src, dst, E);
    k_node <<<(N * 32 + 255) / 256, 256>>>(out, N);
}